// round 11
// baseline (speedup 1.0000x reference)
#include <cuda_runtime.h>
#include <cuda_bf16.h>
#include <cstdint>

#define NN  100000
#define EE  1200000
#define FIN 128
#define HID 64
#define SCAN_TILE 256
#define MAX_PARTS ((NN + SCAN_TILE - 1) / SCAN_TILE)   // 391

// Scratch (static __device__ arrays — no allocation allowed)
__device__ __align__(256) float g_ys [(size_t)NN * HID];   // layer-0 gemm output (gather source)
__device__ __align__(256) float g_ys2[(size_t)NN * HID];   // layer-1 gemm output (gather source)
__device__ __align__(256) float g_dinv[NN];
__device__ __align__(256) int   g_cnt[NN];
__device__ __align__(256) int   g_off[NN + 1];
__device__ __align__(256) int   g_cur[NN];
__device__ __align__(256) int   g_part[MAX_PARTS];
__device__ __align__(256) int   g_srcs[EE];                // dst-sorted source ids (CSR)
__device__ __align__(256) float g_s1[NN];                  // scalar layer source (pre-scaled by dinv)
__device__ int g_is64;

// ---------- f32x2 packed-FMA helpers ----------
__device__ __forceinline__ unsigned long long ffma2(unsigned long long a,
                                                    unsigned long long b,
                                                    unsigned long long c) {
    unsigned long long d;
    asm("fma.rn.f32x2 %0, %1, %2, %3;" : "=l"(d) : "l"(a), "l"(b), "l"(c));
    return d;
}
__device__ __forceinline__ unsigned long long dup2(float x) {
    unsigned long long d;
    unsigned int u = __float_as_uint(x);
    asm("mov.b64 %0, {%1, %1};" : "=l"(d) : "r"(u));
    return d;
}

__device__ __forceinline__ int edge_at(const void* ei, int is64, size_t idx) {
    if (is64) return (int)((const long long*)ei)[idx];
    return ((const int*)ei)[idx];
}

// ---------- zero + edge-dtype detection (merged) ----------
__global__ void k_zero_detect(const long long* ei, int e, int n) {
    int i = blockIdx.x * blockDim.x + threadIdx.x;
    if (i < n) g_cnt[i] = 0;
    if (blockIdx.x == 0 && threadIdx.x < 32) {
        int t = threadIdx.x;
        int m = e < 32 ? e : 32;
        int bad = 0;
        if (t < m) {
            long long v = ei[t];
            if (v < 0 || v >= NN) bad = 1;
        }
        unsigned int anybad = __ballot_sync(0xffffffffu, bad);
        if (t == 0) g_is64 = (anybad == 0u);
    }
}

// ---------- CSR build: histogram (2 edges/thread) ----------
__global__ void k_count(const void* ei, int e) {
    int i = blockIdx.x * blockDim.x + threadIdx.x;
    int is64 = g_is64;
    if (!(e & 1)) {                       // even e: vector path, 16B/8B aligned
        int i2 = i * 2;
        if (i2 >= e) return;
        int d0, d1;
        if (is64) {
            ulonglong2 v = reinterpret_cast<const ulonglong2*>(ei)[((size_t)e + i2) >> 1];
            d0 = (int)v.x; d1 = (int)v.y;
        } else {
            int2 v = reinterpret_cast<const int2*>(ei)[((size_t)e + i2) >> 1];
            d0 = v.x; d1 = v.y;
        }
        if (d0 == d1) {
            atomicAdd(&g_cnt[d0], 2);
        } else {
            atomicAdd(&g_cnt[d0], 1);
            atomicAdd(&g_cnt[d1], 1);
        }
    } else {                              // odd e: scalar fallback
        if (i >= e) return;
        int dst = edge_at(ei, is64, (size_t)e + i);
        atomicAdd(&g_cnt[dst], 1);
    }
}

__global__ __launch_bounds__(SCAN_TILE) void k_blocksum(int n) {
    __shared__ int wsum[SCAN_TILE / 32];
    int t = threadIdx.x;
    int i = blockIdx.x * SCAN_TILE + t;
    int v = (i < n) ? g_cnt[i] : 0;
#pragma unroll
    for (int d = 16; d > 0; d >>= 1) v += __shfl_down_sync(0xffffffffu, v, d);
    if ((t & 31) == 0) wsum[t >> 5] = v;
    __syncthreads();
    if (t < SCAN_TILE / 32) {
        int s = wsum[t];
#pragma unroll
        for (int d = (SCAN_TILE / 64); d > 0; d >>= 1)
            s += __shfl_down_sync(0xffu, s, d);
        if (t == 0) g_part[blockIdx.x] = s;
    }
}

// merged: per-block prefix over g_part (warp 0) + intra-block scan; emits off/cur/dinv
__global__ __launch_bounds__(SCAN_TILE) void k_finaloff(int nb, int n) {
    __shared__ int wexc[SCAN_TILE / 32];
    __shared__ int s_base;
    int t = threadIdx.x;

    if (t < 32) {                          // prefix of partials before this block
        int sum = 0;
        for (int i = t; i < blockIdx.x; i += 32) sum += g_part[i];
#pragma unroll
        for (int d = 16; d > 0; d >>= 1) sum += __shfl_down_sync(0xffffffffu, sum, d);
        if (t == 0) s_base = sum;
    }

    int i = blockIdx.x * SCAN_TILE + t;
    int c = (i < n) ? g_cnt[i] : 0;
    int lane = t & 31, warp = t >> 5;
    int inc = c;
#pragma unroll
    for (int d = 1; d < 32; d <<= 1) {
        int v = __shfl_up_sync(0xffffffffu, inc, d);
        if (lane >= d) inc += v;
    }
    if (lane == 31) wexc[warp] = inc;
    __syncthreads();
    if (t < SCAN_TILE / 32) {
        int v = wexc[t];
        int e2 = v;
#pragma unroll
        for (int d = 1; d < SCAN_TILE / 32; d <<= 1) {
            int u = __shfl_up_sync(0xffu, e2, d);
            if (t >= d) e2 += u;
        }
        wexc[t] = e2 - v;
    }
    __syncthreads();

    int off = s_base + wexc[warp] + (inc - c);
    if (i < n) {
        g_off[i] = off;
        g_cur[i] = off;
        g_dinv[i] = rsqrtf(1.0f + (float)c);
    }
    if (blockIdx.x == nb - 1 && t == SCAN_TILE - 1)
        g_off[n] = off + c;
}

// ---------- fill (2 edges/thread) ----------
__global__ void k_fill(const void* ei, int e) {
    int i = blockIdx.x * blockDim.x + threadIdx.x;
    int is64 = g_is64;
    if (!(e & 1)) {
        int i2 = i * 2;
        if (i2 >= e) return;
        int s0, s1, d0, d1;
        if (is64) {
            ulonglong2 sv = reinterpret_cast<const ulonglong2*>(ei)[(size_t)i2 >> 1];
            ulonglong2 dv = reinterpret_cast<const ulonglong2*>(ei)[((size_t)e + i2) >> 1];
            s0 = (int)sv.x; s1 = (int)sv.y;
            d0 = (int)dv.x; d1 = (int)dv.y;
        } else {
            int2 sv = reinterpret_cast<const int2*>(ei)[(size_t)i2 >> 1];
            int2 dv = reinterpret_cast<const int2*>(ei)[((size_t)e + i2) >> 1];
            s0 = sv.x; s1 = sv.y;
            d0 = dv.x; d1 = dv.y;
        }
        if (d0 == d1) {
            int pos = atomicAdd(&g_cur[d0], 2);
            g_srcs[pos] = s0;
            g_srcs[pos + 1] = s1;
        } else {
            g_srcs[atomicAdd(&g_cur[d0], 1)] = s0;
            g_srcs[atomicAdd(&g_cur[d1], 1)] = s1;
        }
    } else {
        if (i >= e) return;
        int src = edge_at(ei, is64, (size_t)i);
        int dst = edge_at(ei, is64, (size_t)e + i);
        g_srcs[atomicAdd(&g_cur[dst], 1)] = src;
    }
}

// ---------- normalized pull of one node-part: acc = dv*(dv*self + sum du*nb) ----------
__device__ __forceinline__ float4 aggr_part(const float* __restrict__ src,
                                            int node, int part) {
    float dv = g_dinv[node];
    float4 self = *reinterpret_cast<const float4*>(src + (size_t)node * HID + part * 4);
    float4 acc;
    acc.x = self.x * dv; acc.y = self.y * dv;
    acc.z = self.z * dv; acc.w = self.w * dv;

    int j   = g_off[node];
    int end = g_off[node + 1];
    for (; j + 4 <= end; j += 4) {
        int s0 = g_srcs[j + 0], s1 = g_srcs[j + 1];
        int s2 = g_srcs[j + 2], s3 = g_srcs[j + 3];
        float d0 = g_dinv[s0], d1 = g_dinv[s1], d2 = g_dinv[s2], d3 = g_dinv[s3];
        float4 v0 = *reinterpret_cast<const float4*>(src + (size_t)s0 * HID + part * 4);
        float4 v1 = *reinterpret_cast<const float4*>(src + (size_t)s1 * HID + part * 4);
        float4 v2 = *reinterpret_cast<const float4*>(src + (size_t)s2 * HID + part * 4);
        float4 v3 = *reinterpret_cast<const float4*>(src + (size_t)s3 * HID + part * 4);
        acc.x = fmaf(d0, v0.x, fmaf(d1, v1.x, fmaf(d2, v2.x, fmaf(d3, v3.x, acc.x))));
        acc.y = fmaf(d0, v0.y, fmaf(d1, v1.y, fmaf(d2, v2.y, fmaf(d3, v3.y, acc.y))));
        acc.z = fmaf(d0, v0.z, fmaf(d1, v1.z, fmaf(d2, v2.z, fmaf(d3, v3.z, acc.z))));
        acc.w = fmaf(d0, v0.w, fmaf(d1, v1.w, fmaf(d2, v2.w, fmaf(d3, v3.w, acc.w))));
    }
    for (; j < end; j++) {
        int s = g_srcs[j];
        float du = g_dinv[s];
        float4 v = *reinterpret_cast<const float4*>(src + (size_t)s * HID + part * 4);
        acc.x = fmaf(du, v.x, acc.x); acc.y = fmaf(du, v.y, acc.y);
        acc.z = fmaf(du, v.z, acc.z); acc.w = fmaf(du, v.w, acc.w);
    }
    acc.x *= dv; acc.y *= dv; acc.z *= dv; acc.w *= dv;
    return acc;
}

// ---------- tiled SGEMM (f32x2 packed): ys = A @ W  (layer 0, K=128) ----------
template <int K>
__global__ __launch_bounds__(256)
void k_gemm(const float* __restrict__ A, const float* __restrict__ W, int n) {
    constexpr int BM = 128, BN = 64, BK = 16;
    __shared__ float Ws[K * BN];
    __shared__ float As[BK][BM];

    int tid = threadIdx.x;
    for (int i = tid; i < (K * BN) / 4; i += 256)
        reinterpret_cast<float4*>(Ws)[i] = reinterpret_cast<const float4*>(W)[i];

    int tx = tid & 15;
    int ty = tid >> 4;
    int row0 = blockIdx.x * BM;

    unsigned long long acc2[4][4];
#pragma unroll
    for (int r = 0; r < 4; r++)
#pragma unroll
        for (int c = 0; c < 4; c++) acc2[r][c] = 0ULL;

    for (int k0 = 0; k0 < K; k0 += BK) {
        __syncthreads();
#pragma unroll
        for (int l = 0; l < 2; l++) {
            int lin = tid + l * 256;
            int row = lin & 127;
            int kq  = lin >> 7;
            int grow = row0 + row;
            float4 v = make_float4(0.f, 0.f, 0.f, 0.f);
            if (grow < n)
                v = *reinterpret_cast<const float4*>(A + (size_t)grow * K + k0 + kq * 4);
            As[kq * 4 + 0][row] = v.x;
            As[kq * 4 + 1][row] = v.y;
            As[kq * 4 + 2][row] = v.z;
            As[kq * 4 + 3][row] = v.w;
        }
        __syncthreads();

#pragma unroll
        for (int k = 0; k < BK; k++) {
            float4 b = *reinterpret_cast<const float4*>(&Ws[(k0 + k) * BN + tx * 4]);
            unsigned long long bp[4] = {dup2(b.x), dup2(b.y), dup2(b.z), dup2(b.w)};
            const ulonglong2* ar = reinterpret_cast<const ulonglong2*>(&As[k][ty * 8]);
            ulonglong2 a01 = ar[0];
            ulonglong2 a23 = ar[1];
            unsigned long long ap[4] = {a01.x, a01.y, a23.x, a23.y};
#pragma unroll
            for (int r = 0; r < 4; r++)
#pragma unroll
                for (int c = 0; c < 4; c++)
                    acc2[r][c] = ffma2(ap[r], bp[c], acc2[r][c]);
        }
    }

#pragma unroll
    for (int r = 0; r < 4; r++) {
        int ge = row0 + ty * 8 + 2 * r;
        float2 c0 = *reinterpret_cast<float2*>(&acc2[r][0]);
        float2 c1 = *reinterpret_cast<float2*>(&acc2[r][1]);
        float2 c2 = *reinterpret_cast<float2*>(&acc2[r][2]);
        float2 c3 = *reinterpret_cast<float2*>(&acc2[r][3]);
        if (ge < n) {
            float4 o = make_float4(c0.x, c1.x, c2.x, c3.x);
            *reinterpret_cast<float4*>(g_ys + (size_t)ge * HID + tx * 4) = o;
        }
        if (ge + 1 < n) {
            float4 o = make_float4(c0.y, c1.y, c2.y, c3.y);
            *reinterpret_cast<float4*>(g_ys + (size_t)(ge + 1) * HID + tx * 4) = o;
        }
    }
}

// ---------- FUSED: aggr(ys) -> relu(+b0) -> @W1 -> ys2   (K=HID=64) ----------
__global__ __launch_bounds__(256)
void k_fused_ag(const float* __restrict__ W, const float* __restrict__ bias, int n) {
    constexpr int BM = 128, BN = 64, K = 64, AST = 132;
    __shared__ float Ws[K * BN];          // 16 KB
    __shared__ float As[K][AST];          // 33.8 KB, k-major transposed A tile

    int tid = threadIdx.x;
    for (int i = tid; i < (K * BN) / 4; i += 256)
        reinterpret_cast<float4*>(Ws)[i] = reinterpret_cast<const float4*>(W)[i];

    int row0 = blockIdx.x * BM;
    int part = tid & 15;      // feature part: 4 floats
    int grp  = tid >> 4;      // node group within pass

    float4 bk = *reinterpret_cast<const float4*>(bias + part * 4);

    // aggregation phase: 8 passes x 16 nodes
#pragma unroll 1
    for (int p = 0; p < 8; p++) {
        int nl = p * 16 + grp;
        int node = row0 + nl;
        float4 a = make_float4(0.f, 0.f, 0.f, 0.f);
        if (node < n) {
            a = aggr_part(g_ys, node, part);
            a.x = fmaxf(a.x + bk.x, 0.0f);
            a.y = fmaxf(a.y + bk.y, 0.0f);
            a.z = fmaxf(a.z + bk.z, 0.0f);
            a.w = fmaxf(a.w + bk.w, 0.0f);
        }
        As[part * 4 + 0][nl] = a.x;
        As[part * 4 + 1][nl] = a.y;
        As[part * 4 + 2][nl] = a.z;
        As[part * 4 + 3][nl] = a.w;
    }
    __syncthreads();

    // GEMM phase
    int tx = tid & 15;
    int ty = tid >> 4;
    unsigned long long acc2[4][4];
#pragma unroll
    for (int r = 0; r < 4; r++)
#pragma unroll
        for (int c = 0; c < 4; c++) acc2[r][c] = 0ULL;

#pragma unroll 8
    for (int k = 0; k < K; k++) {
        float4 b = *reinterpret_cast<const float4*>(&Ws[k * BN + tx * 4]);
        unsigned long long bp[4] = {dup2(b.x), dup2(b.y), dup2(b.z), dup2(b.w)};
        const ulonglong2* ar = reinterpret_cast<const ulonglong2*>(&As[k][ty * 8]);
        ulonglong2 a01 = ar[0];
        ulonglong2 a23 = ar[1];
        unsigned long long ap[4] = {a01.x, a01.y, a23.x, a23.y};
#pragma unroll
        for (int r = 0; r < 4; r++)
#pragma unroll
            for (int c = 0; c < 4; c++)
                acc2[r][c] = ffma2(ap[r], bp[c], acc2[r][c]);
    }

#pragma unroll
    for (int r = 0; r < 4; r++) {
        int ge = row0 + ty * 8 + 2 * r;
        float2 c0 = *reinterpret_cast<float2*>(&acc2[r][0]);
        float2 c1 = *reinterpret_cast<float2*>(&acc2[r][1]);
        float2 c2 = *reinterpret_cast<float2*>(&acc2[r][2]);
        float2 c3 = *reinterpret_cast<float2*>(&acc2[r][3]);
        if (ge < n) {
            float4 o = make_float4(c0.x, c1.x, c2.x, c3.x);
            *reinterpret_cast<float4*>(g_ys2 + (size_t)ge * HID + tx * 4) = o;
        }
        if (ge + 1 < n) {
            float4 o = make_float4(c0.y, c1.y, c2.y, c3.y);
            *reinterpret_cast<float4*>(g_ys2 + (size_t)(ge + 1) * HID + tx * 4) = o;
        }
    }
}

// ---------- FUSED: aggr(ys2) -> relu(+b1) -> dot W2 -> s1 = dinv * dot ----------
__global__ void k_fused_b(const float* __restrict__ b1,
                          const float* __restrict__ W2, int n) {
    int t = blockIdx.x * blockDim.x + threadIdx.x;
    int node = t >> 4;
    if (node >= n) return;
    int part = t & 15;

    float4 a = aggr_part(g_ys2, node, part);
    float4 b = __ldg(reinterpret_cast<const float4*>(b1 + part * 4));
    float4 w = __ldg(reinterpret_cast<const float4*>(W2 + part * 4));
    float s = fmaxf(a.x + b.x, 0.0f) * w.x
            + fmaxf(a.y + b.y, 0.0f) * w.y
            + fmaxf(a.z + b.z, 0.0f) * w.z
            + fmaxf(a.w + b.w, 0.0f) * w.w;
#pragma unroll
    for (int d = 8; d > 0; d >>= 1)
        s += __shfl_down_sync(0xffffffffu, s, d, 16);
    if (part == 0) g_s1[node] = s * g_dinv[node];
}

// ---------- FUSED: scalar aggr(s1) -> +b2 -> MLP head -> out ----------
__global__ void k_fused_c(const float* __restrict__ b2,
                          const float* __restrict__ Wm1,
                          const float* __restrict__ bm1,
                          const float* __restrict__ Wm2,
                          const float* __restrict__ bm2,
                          float* __restrict__ out, int n) {
    int i = blockIdx.x * blockDim.x + threadIdx.x;
    if (i >= n) return;
    float s = g_s1[i];
    int j   = g_off[i];
    int end = g_off[i + 1];
    for (; j + 4 <= end; j += 4) {
        float v0 = g_s1[g_srcs[j + 0]];
        float v1 = g_s1[g_srcs[j + 1]];
        float v2 = g_s1[g_srcs[j + 2]];
        float v3 = g_s1[g_srcs[j + 3]];
        s += v0 + v1 + v2 + v3;
    }
    for (; j < end; j++) s += g_s1[g_srcs[j]];
    float h2 = fmaf(s, g_dinv[i], __ldg(b2));

    const float4* w1 = reinterpret_cast<const float4*>(Wm1);
    const float4* bb = reinterpret_cast<const float4*>(bm1);
    const float4* w2 = reinterpret_cast<const float4*>(Wm2);
    float o = __ldg(bm2);
#pragma unroll
    for (int j4 = 0; j4 < HID / 4; j4++) {
        float4 a = __ldg(&w1[j4]);
        float4 b = __ldg(&bb[j4]);
        float4 c = __ldg(&w2[j4]);
        o += fmaxf(fmaf(h2, a.x, b.x), 0.0f) * c.x;
        o += fmaxf(fmaf(h2, a.y, b.y), 0.0f) * c.y;
        o += fmaxf(fmaf(h2, a.z, b.z), 0.0f) * c.z;
        o += fmaxf(fmaf(h2, a.w, b.w), 0.0f) * c.w;
    }
    out[i] = o;
}

extern "C" void kernel_launch(void* const* d_in, const int* in_sizes, int n_in,
                              void* d_out, int out_size) {
    const float* x   = (const float*)d_in[0];
    const void*  ei  = d_in[1];
    const float* W0  = (const float*)d_in[2];
    const float* b0  = (const float*)d_in[3];
    const float* W1  = (const float*)d_in[4];
    const float* b1  = (const float*)d_in[5];
    const float* W2  = (const float*)d_in[6];
    const float* b2  = (const float*)d_in[7];
    const float* Wm1 = (const float*)d_in[8];
    const float* bm1 = (const float*)d_in[9];
    const float* Wm2 = (const float*)d_in[10];
    const float* bm2 = (const float*)d_in[11];
    float* out = (float*)d_out;

    int n = in_sizes[0] / FIN;   // 100000
    int e = in_sizes[1] / 2;     // 1200000
    int nb = (n + SCAN_TILE - 1) / SCAN_TILE;   // 391

    static cudaStream_t sB = nullptr;
    static cudaEvent_t evFork = nullptr, evJoin = nullptr;
    if (sB == nullptr) {
        cudaStreamCreateWithFlags(&sB, cudaStreamNonBlocking);
        cudaEventCreateWithFlags(&evFork, cudaEventDisableTiming);
        cudaEventCreateWithFlags(&evJoin, cudaEventDisableTiming);
    }

    int gemm_grid = (n + 127) / 128;
    int node16_grid = (n * 16 + 255) / 256;
    int epair = (e & 1) ? e : e / 2;            // threads for 2-edge kernels

    // ---- fork: GEMM0 (independent of graph structure) on sB ----
    cudaEventRecord(evFork, 0);
    cudaStreamWaitEvent(sB, evFork, 0);
    k_gemm<FIN><<<gemm_grid, 256, 0, sB>>>(x, W0, n);
    cudaEventRecord(evJoin, sB);

    // ---- CSR build on default stream (concurrent with GEMM0) ----
    k_zero_detect<<<(n + 255) / 256, 256>>>((const long long*)ei, e, n);
    k_count<<<(epair + 255) / 256, 256>>>(ei, e);
    k_blocksum<<<nb, SCAN_TILE>>>(n);
    k_finaloff<<<nb, SCAN_TILE>>>(nb, n);
    k_fill <<<(epair + 255) / 256, 256>>>(ei, e);

    // ---- join ----
    cudaStreamWaitEvent(0, evJoin, 0);

    // fused layer chain
    k_fused_ag<<<gemm_grid, 256>>>(W1, b0, n);                   // aggr0 + relu + @W1
    k_fused_b <<<node16_grid, 256>>>(b1, W2, n);                 // aggr1 + relu + .W2
    k_fused_c <<<(n + 255) / 256, 256>>>(b2, Wm1, bm1, Wm2, bm2, out, n);
}

// round 12
// speedup vs baseline: 1.0672x; 1.0672x over previous
#include <cuda_runtime.h>
#include <cuda_fp16.h>
#include <cstdint>

#define NN  100000
#define EE  1200000
#define FIN 128
#define HID 64
#define SCAN_TILE 256
#define MAX_PARTS ((NN + SCAN_TILE - 1) / SCAN_TILE)   // 391

// Scratch (static __device__ arrays — no allocation allowed)
__device__ __align__(256) __half g_ysh [(size_t)NN * HID];  // layer-0 out (fp16 gather source)
__device__ __align__(256) __half g_ys2h[(size_t)NN * HID];  // layer-1 out (fp16 gather source)
__device__ __align__(256) float g_dinv[NN];
__device__ __align__(256) int   g_cnt[NN];
__device__ __align__(256) int   g_off[NN + 1];
__device__ __align__(256) int   g_cur[NN];
__device__ __align__(256) int   g_part[MAX_PARTS];
__device__ __align__(256) int   g_srcs[EE];                // dst-sorted source ids (CSR)
__device__ __align__(256) float g_s1[NN];                  // scalar layer source
__device__ int g_is64;

// ---------- f32x2 packed-FMA helpers ----------
__device__ __forceinline__ unsigned long long ffma2(unsigned long long a,
                                                    unsigned long long b,
                                                    unsigned long long c) {
    unsigned long long d;
    asm("fma.rn.f32x2 %0, %1, %2, %3;" : "=l"(d) : "l"(a), "l"(b), "l"(c));
    return d;
}
__device__ __forceinline__ unsigned long long dup2(float x) {
    unsigned long long d;
    unsigned int u = __float_as_uint(x);
    asm("mov.b64 %0, {%1, %1};" : "=l"(d) : "r"(u));
    return d;
}

// ---------- fp16 pack/unpack (8B per 4 elements) ----------
__device__ __forceinline__ float4 ld_half4(const __half* p) {
    uint2 u = *reinterpret_cast<const uint2*>(p);      // single LDG.64
    __half2 h01 = *reinterpret_cast<__half2*>(&u.x);
    __half2 h23 = *reinterpret_cast<__half2*>(&u.y);
    float2 f01 = __half22float2(h01);
    float2 f23 = __half22float2(h23);
    return make_float4(f01.x, f01.y, f23.x, f23.y);
}
__device__ __forceinline__ void st_half4(__half* p, float4 v) {
    __half2 h01 = __floats2half2_rn(v.x, v.y);
    __half2 h23 = __floats2half2_rn(v.z, v.w);
    uint2 u;
    u.x = *reinterpret_cast<unsigned int*>(&h01);
    u.y = *reinterpret_cast<unsigned int*>(&h23);
    *reinterpret_cast<uint2*>(p) = u;                  // single STG.64
}

__device__ __forceinline__ int edge_at(const void* ei, int is64, size_t idx) {
    if (is64) return (int)((const long long*)ei)[idx];
    return ((const int*)ei)[idx];
}

// ---------- zero + edge-dtype detection (merged) ----------
__global__ void k_zero_detect(const long long* ei, int e, int n) {
    int i = blockIdx.x * blockDim.x + threadIdx.x;
    if (i < n) g_cnt[i] = 0;
    if (blockIdx.x == 0 && threadIdx.x < 32) {
        int t = threadIdx.x;
        int m = e < 32 ? e : 32;
        int bad = 0;
        if (t < m) {
            long long v = ei[t];
            if (v < 0 || v >= NN) bad = 1;
        }
        unsigned int anybad = __ballot_sync(0xffffffffu, bad);
        if (t == 0) g_is64 = (anybad == 0u);
    }
}

// ---------- CSR build: histogram (2 edges/thread) ----------
__global__ void k_count(const void* ei, int e) {
    int i = blockIdx.x * blockDim.x + threadIdx.x;
    int is64 = g_is64;
    if (!(e & 1)) {
        int i2 = i * 2;
        if (i2 >= e) return;
        int d0, d1;
        if (is64) {
            ulonglong2 v = reinterpret_cast<const ulonglong2*>(ei)[((size_t)e + i2) >> 1];
            d0 = (int)v.x; d1 = (int)v.y;
        } else {
            int2 v = reinterpret_cast<const int2*>(ei)[((size_t)e + i2) >> 1];
            d0 = v.x; d1 = v.y;
        }
        if (d0 == d1) {
            atomicAdd(&g_cnt[d0], 2);
        } else {
            atomicAdd(&g_cnt[d0], 1);
            atomicAdd(&g_cnt[d1], 1);
        }
    } else {
        if (i >= e) return;
        int dst = edge_at(ei, is64, (size_t)e + i);
        atomicAdd(&g_cnt[dst], 1);
    }
}

__global__ __launch_bounds__(SCAN_TILE) void k_blocksum(int n) {
    __shared__ int wsum[SCAN_TILE / 32];
    int t = threadIdx.x;
    int i = blockIdx.x * SCAN_TILE + t;
    int v = (i < n) ? g_cnt[i] : 0;
#pragma unroll
    for (int d = 16; d > 0; d >>= 1) v += __shfl_down_sync(0xffffffffu, v, d);
    if ((t & 31) == 0) wsum[t >> 5] = v;
    __syncthreads();
    if (t < SCAN_TILE / 32) {
        int s = wsum[t];
#pragma unroll
        for (int d = (SCAN_TILE / 64); d > 0; d >>= 1)
            s += __shfl_down_sync(0xffu, s, d);
        if (t == 0) g_part[blockIdx.x] = s;
    }
}

// merged: per-block prefix over g_part (warp 0) + intra-block scan; emits off/cur/dinv
__global__ __launch_bounds__(SCAN_TILE) void k_finaloff(int nb, int n) {
    __shared__ int wexc[SCAN_TILE / 32];
    __shared__ int s_base;
    int t = threadIdx.x;

    if (t < 32) {
        int sum = 0;
        for (int i = t; i < blockIdx.x; i += 32) sum += g_part[i];
#pragma unroll
        for (int d = 16; d > 0; d >>= 1) sum += __shfl_down_sync(0xffffffffu, sum, d);
        if (t == 0) s_base = sum;
    }

    int i = blockIdx.x * SCAN_TILE + t;
    int c = (i < n) ? g_cnt[i] : 0;
    int lane = t & 31, warp = t >> 5;
    int inc = c;
#pragma unroll
    for (int d = 1; d < 32; d <<= 1) {
        int v = __shfl_up_sync(0xffffffffu, inc, d);
        if (lane >= d) inc += v;
    }
    if (lane == 31) wexc[warp] = inc;
    __syncthreads();
    if (t < SCAN_TILE / 32) {
        int v = wexc[t];
        int e2 = v;
#pragma unroll
        for (int d = 1; d < SCAN_TILE / 32; d <<= 1) {
            int u = __shfl_up_sync(0xffu, e2, d);
            if (t >= d) e2 += u;
        }
        wexc[t] = e2 - v;
    }
    __syncthreads();

    int off = s_base + wexc[warp] + (inc - c);
    if (i < n) {
        g_off[i] = off;
        g_cur[i] = off;
        g_dinv[i] = rsqrtf(1.0f + (float)c);
    }
    if (blockIdx.x == nb - 1 && t == SCAN_TILE - 1)
        g_off[n] = off + c;
}

// ---------- fill (2 edges/thread) ----------
__global__ void k_fill(const void* ei, int e) {
    int i = blockIdx.x * blockDim.x + threadIdx.x;
    int is64 = g_is64;
    if (!(e & 1)) {
        int i2 = i * 2;
        if (i2 >= e) return;
        int s0, s1, d0, d1;
        if (is64) {
            ulonglong2 sv = reinterpret_cast<const ulonglong2*>(ei)[(size_t)i2 >> 1];
            ulonglong2 dv = reinterpret_cast<const ulonglong2*>(ei)[((size_t)e + i2) >> 1];
            s0 = (int)sv.x; s1 = (int)sv.y;
            d0 = (int)dv.x; d1 = (int)dv.y;
        } else {
            int2 sv = reinterpret_cast<const int2*>(ei)[(size_t)i2 >> 1];
            int2 dv = reinterpret_cast<const int2*>(ei)[((size_t)e + i2) >> 1];
            s0 = sv.x; s1 = sv.y;
            d0 = dv.x; d1 = dv.y;
        }
        if (d0 == d1) {
            int pos = atomicAdd(&g_cur[d0], 2);
            g_srcs[pos] = s0;
            g_srcs[pos + 1] = s1;
        } else {
            g_srcs[atomicAdd(&g_cur[d0], 1)] = s0;
            g_srcs[atomicAdd(&g_cur[d1], 1)] = s1;
        }
    } else {
        if (i >= e) return;
        int src = edge_at(ei, is64, (size_t)i);
        int dst = edge_at(ei, is64, (size_t)e + i);
        g_srcs[atomicAdd(&g_cur[dst], 1)] = src;
    }
}

// ---------- normalized pull of one node-part from fp16 source ----------
__device__ __forceinline__ float4 aggr_part_h(const __half* __restrict__ src,
                                              int node, int part) {
    float dv = g_dinv[node];
    float4 self = ld_half4(src + (size_t)node * HID + part * 4);
    float4 acc;
    acc.x = self.x * dv; acc.y = self.y * dv;
    acc.z = self.z * dv; acc.w = self.w * dv;

    int j   = g_off[node];
    int end = g_off[node + 1];
    for (; j + 4 <= end; j += 4) {
        int s0 = g_srcs[j + 0], s1 = g_srcs[j + 1];
        int s2 = g_srcs[j + 2], s3 = g_srcs[j + 3];
        float d0 = g_dinv[s0], d1 = g_dinv[s1], d2 = g_dinv[s2], d3 = g_dinv[s3];
        float4 v0 = ld_half4(src + (size_t)s0 * HID + part * 4);
        float4 v1 = ld_half4(src + (size_t)s1 * HID + part * 4);
        float4 v2 = ld_half4(src + (size_t)s2 * HID + part * 4);
        float4 v3 = ld_half4(src + (size_t)s3 * HID + part * 4);
        acc.x = fmaf(d0, v0.x, fmaf(d1, v1.x, fmaf(d2, v2.x, fmaf(d3, v3.x, acc.x))));
        acc.y = fmaf(d0, v0.y, fmaf(d1, v1.y, fmaf(d2, v2.y, fmaf(d3, v3.y, acc.y))));
        acc.z = fmaf(d0, v0.z, fmaf(d1, v1.z, fmaf(d2, v2.z, fmaf(d3, v3.z, acc.z))));
        acc.w = fmaf(d0, v0.w, fmaf(d1, v1.w, fmaf(d2, v2.w, fmaf(d3, v3.w, acc.w))));
    }
    for (; j < end; j++) {
        int s = g_srcs[j];
        float du = g_dinv[s];
        float4 v = ld_half4(src + (size_t)s * HID + part * 4);
        acc.x = fmaf(du, v.x, acc.x); acc.y = fmaf(du, v.y, acc.y);
        acc.z = fmaf(du, v.z, acc.z); acc.w = fmaf(du, v.w, acc.w);
    }
    acc.x *= dv; acc.y *= dv; acc.z *= dv; acc.w *= dv;
    return acc;
}

// ---------- tiled SGEMM (f32x2 packed): ysh = fp16(A @ W)  (layer 0, K=128) ----------
template <int K>
__global__ __launch_bounds__(256)
void k_gemm(const float* __restrict__ A, const float* __restrict__ W, int n) {
    constexpr int BM = 128, BN = 64, BK = 16;
    __shared__ float Ws[K * BN];
    __shared__ float As[BK][BM];

    int tid = threadIdx.x;
    for (int i = tid; i < (K * BN) / 4; i += 256)
        reinterpret_cast<float4*>(Ws)[i] = reinterpret_cast<const float4*>(W)[i];

    int tx = tid & 15;
    int ty = tid >> 4;
    int row0 = blockIdx.x * BM;

    unsigned long long acc2[4][4];
#pragma unroll
    for (int r = 0; r < 4; r++)
#pragma unroll
        for (int c = 0; c < 4; c++) acc2[r][c] = 0ULL;

    for (int k0 = 0; k0 < K; k0 += BK) {
        __syncthreads();
#pragma unroll
        for (int l = 0; l < 2; l++) {
            int lin = tid + l * 256;
            int row = lin & 127;
            int kq  = lin >> 7;
            int grow = row0 + row;
            float4 v = make_float4(0.f, 0.f, 0.f, 0.f);
            if (grow < n)
                v = *reinterpret_cast<const float4*>(A + (size_t)grow * K + k0 + kq * 4);
            As[kq * 4 + 0][row] = v.x;
            As[kq * 4 + 1][row] = v.y;
            As[kq * 4 + 2][row] = v.z;
            As[kq * 4 + 3][row] = v.w;
        }
        __syncthreads();

#pragma unroll
        for (int k = 0; k < BK; k++) {
            float4 b = *reinterpret_cast<const float4*>(&Ws[(k0 + k) * BN + tx * 4]);
            unsigned long long bp[4] = {dup2(b.x), dup2(b.y), dup2(b.z), dup2(b.w)};
            const ulonglong2* ar = reinterpret_cast<const ulonglong2*>(&As[k][ty * 8]);
            ulonglong2 a01 = ar[0];
            ulonglong2 a23 = ar[1];
            unsigned long long ap[4] = {a01.x, a01.y, a23.x, a23.y};
#pragma unroll
            for (int r = 0; r < 4; r++)
#pragma unroll
                for (int c = 0; c < 4; c++)
                    acc2[r][c] = ffma2(ap[r], bp[c], acc2[r][c]);
        }
    }

#pragma unroll
    for (int r = 0; r < 4; r++) {
        int ge = row0 + ty * 8 + 2 * r;
        float2 c0 = *reinterpret_cast<float2*>(&acc2[r][0]);
        float2 c1 = *reinterpret_cast<float2*>(&acc2[r][1]);
        float2 c2 = *reinterpret_cast<float2*>(&acc2[r][2]);
        float2 c3 = *reinterpret_cast<float2*>(&acc2[r][3]);
        if (ge < n)
            st_half4(g_ysh + (size_t)ge * HID + tx * 4,
                     make_float4(c0.x, c1.x, c2.x, c3.x));
        if (ge + 1 < n)
            st_half4(g_ysh + (size_t)(ge + 1) * HID + tx * 4,
                     make_float4(c0.y, c1.y, c2.y, c3.y));
    }
}

// ---------- FUSED: aggr(ysh) -> relu(+b0) -> @W1 -> ys2h   (K=HID=64) ----------
__global__ __launch_bounds__(256)
void k_fused_ag(const float* __restrict__ W, const float* __restrict__ bias, int n) {
    constexpr int BM = 128, BN = 64, K = 64, AST = 132;
    __shared__ float Ws[K * BN];          // 16 KB
    __shared__ float As[K][AST];          // 33.8 KB

    int tid = threadIdx.x;
    for (int i = tid; i < (K * BN) / 4; i += 256)
        reinterpret_cast<float4*>(Ws)[i] = reinterpret_cast<const float4*>(W)[i];

    int row0 = blockIdx.x * BM;
    int part = tid & 15;
    int grp  = tid >> 4;

    float4 bk = *reinterpret_cast<const float4*>(bias + part * 4);

#pragma unroll 1
    for (int p = 0; p < 8; p++) {
        int nl = p * 16 + grp;
        int node = row0 + nl;
        float4 a = make_float4(0.f, 0.f, 0.f, 0.f);
        if (node < n) {
            a = aggr_part_h(g_ysh, node, part);
            a.x = fmaxf(a.x + bk.x, 0.0f);
            a.y = fmaxf(a.y + bk.y, 0.0f);
            a.z = fmaxf(a.z + bk.z, 0.0f);
            a.w = fmaxf(a.w + bk.w, 0.0f);
        }
        As[part * 4 + 0][nl] = a.x;
        As[part * 4 + 1][nl] = a.y;
        As[part * 4 + 2][nl] = a.z;
        As[part * 4 + 3][nl] = a.w;
    }
    __syncthreads();

    int tx = tid & 15;
    int ty = tid >> 4;
    unsigned long long acc2[4][4];
#pragma unroll
    for (int r = 0; r < 4; r++)
#pragma unroll
        for (int c = 0; c < 4; c++) acc2[r][c] = 0ULL;

#pragma unroll 8
    for (int k = 0; k < K; k++) {
        float4 b = *reinterpret_cast<const float4*>(&Ws[k * BN + tx * 4]);
        unsigned long long bp[4] = {dup2(b.x), dup2(b.y), dup2(b.z), dup2(b.w)};
        const ulonglong2* ar = reinterpret_cast<const ulonglong2*>(&As[k][ty * 8]);
        ulonglong2 a01 = ar[0];
        ulonglong2 a23 = ar[1];
        unsigned long long ap[4] = {a01.x, a01.y, a23.x, a23.y};
#pragma unroll
        for (int r = 0; r < 4; r++)
#pragma unroll
            for (int c = 0; c < 4; c++)
                acc2[r][c] = ffma2(ap[r], bp[c], acc2[r][c]);
    }

#pragma unroll
    for (int r = 0; r < 4; r++) {
        int ge = row0 + ty * 8 + 2 * r;
        float2 c0 = *reinterpret_cast<float2*>(&acc2[r][0]);
        float2 c1 = *reinterpret_cast<float2*>(&acc2[r][1]);
        float2 c2 = *reinterpret_cast<float2*>(&acc2[r][2]);
        float2 c3 = *reinterpret_cast<float2*>(&acc2[r][3]);
        if (ge < n)
            st_half4(g_ys2h + (size_t)ge * HID + tx * 4,
                     make_float4(c0.x, c1.x, c2.x, c3.x));
        if (ge + 1 < n)
            st_half4(g_ys2h + (size_t)(ge + 1) * HID + tx * 4,
                     make_float4(c0.y, c1.y, c2.y, c3.y));
    }
}

// ---------- FUSED: aggr(ys2h) -> relu(+b1) -> dot W2 -> s1 = dinv * dot ----------
__global__ void k_fused_b(const float* __restrict__ b1,
                          const float* __restrict__ W2, int n) {
    int t = blockIdx.x * blockDim.x + threadIdx.x;
    int node = t >> 4;
    if (node >= n) return;
    int part = t & 15;

    float4 a = aggr_part_h(g_ys2h, node, part);
    float4 b = __ldg(reinterpret_cast<const float4*>(b1 + part * 4));
    float4 w = __ldg(reinterpret_cast<const float4*>(W2 + part * 4));
    float s = fmaxf(a.x + b.x, 0.0f) * w.x
            + fmaxf(a.y + b.y, 0.0f) * w.y
            + fmaxf(a.z + b.z, 0.0f) * w.z
            + fmaxf(a.w + b.w, 0.0f) * w.w;
#pragma unroll
    for (int d = 8; d > 0; d >>= 1)
        s += __shfl_down_sync(0xffffffffu, s, d, 16);
    if (part == 0) g_s1[node] = s * g_dinv[node];
}

// ---------- FUSED: scalar aggr(s1) -> +b2 -> MLP head -> out ----------
__global__ void k_fused_c(const float* __restrict__ b2,
                          const float* __restrict__ Wm1,
                          const float* __restrict__ bm1,
                          const float* __restrict__ Wm2,
                          const float* __restrict__ bm2,
                          float* __restrict__ out, int n) {
    int i = blockIdx.x * blockDim.x + threadIdx.x;
    if (i >= n) return;
    float s = g_s1[i];
    int j   = g_off[i];
    int end = g_off[i + 1];
    for (; j + 4 <= end; j += 4) {
        float v0 = g_s1[g_srcs[j + 0]];
        float v1 = g_s1[g_srcs[j + 1]];
        float v2 = g_s1[g_srcs[j + 2]];
        float v3 = g_s1[g_srcs[j + 3]];
        s += v0 + v1 + v2 + v3;
    }
    for (; j < end; j++) s += g_s1[g_srcs[j]];
    float h2 = fmaf(s, g_dinv[i], __ldg(b2));

    const float4* w1 = reinterpret_cast<const float4*>(Wm1);
    const float4* bb = reinterpret_cast<const float4*>(bm1);
    const float4* w2 = reinterpret_cast<const float4*>(Wm2);
    float o = __ldg(bm2);
#pragma unroll
    for (int j4 = 0; j4 < HID / 4; j4++) {
        float4 a = __ldg(&w1[j4]);
        float4 b = __ldg(&bb[j4]);
        float4 c = __ldg(&w2[j4]);
        o += fmaxf(fmaf(h2, a.x, b.x), 0.0f) * c.x;
        o += fmaxf(fmaf(h2, a.y, b.y), 0.0f) * c.y;
        o += fmaxf(fmaf(h2, a.z, b.z), 0.0f) * c.z;
        o += fmaxf(fmaf(h2, a.w, b.w), 0.0f) * c.w;
    }
    out[i] = o;
}

extern "C" void kernel_launch(void* const* d_in, const int* in_sizes, int n_in,
                              void* d_out, int out_size) {
    const float* x   = (const float*)d_in[0];
    const void*  ei  = d_in[1];
    const float* W0  = (const float*)d_in[2];
    const float* b0  = (const float*)d_in[3];
    const float* W1  = (const float*)d_in[4];
    const float* b1  = (const float*)d_in[5];
    const float* W2  = (const float*)d_in[6];
    const float* b2  = (const float*)d_in[7];
    const float* Wm1 = (const float*)d_in[8];
    const float* bm1 = (const float*)d_in[9];
    const float* Wm2 = (const float*)d_in[10];
    const float* bm2 = (const float*)d_in[11];
    float* out = (float*)d_out;

    int n = in_sizes[0] / FIN;   // 100000
    int e = in_sizes[1] / 2;     // 1200000
    int nb = (n + SCAN_TILE - 1) / SCAN_TILE;   // 391

    static cudaStream_t sB = nullptr;
    static cudaEvent_t evFork = nullptr, evJoin = nullptr;
    if (sB == nullptr) {
        cudaStreamCreateWithFlags(&sB, cudaStreamNonBlocking);
        cudaEventCreateWithFlags(&evFork, cudaEventDisableTiming);
        cudaEventCreateWithFlags(&evJoin, cudaEventDisableTiming);
    }

    int gemm_grid = (n + 127) / 128;
    int node16_grid = (n * 16 + 255) / 256;
    int epair = (e & 1) ? e : e / 2;

    // ---- fork: GEMM0 (independent of graph structure) on sB ----
    cudaEventRecord(evFork, 0);
    cudaStreamWaitEvent(sB, evFork, 0);
    k_gemm<FIN><<<gemm_grid, 256, 0, sB>>>(x, W0, n);
    cudaEventRecord(evJoin, sB);

    // ---- CSR build on default stream (concurrent with GEMM0) ----
    k_zero_detect<<<(n + 255) / 256, 256>>>((const long long*)ei, e, n);
    k_count<<<(epair + 255) / 256, 256>>>(ei, e);
    k_blocksum<<<nb, SCAN_TILE>>>(n);
    k_finaloff<<<nb, SCAN_TILE>>>(nb, n);
    k_fill <<<(epair + 255) / 256, 256>>>(ei, e);

    // ---- join ----
    cudaStreamWaitEvent(0, evJoin, 0);

    // fused layer chain
    k_fused_ag<<<gemm_grid, 256>>>(W1, b0, n);                   // aggr0 + relu + @W1
    k_fused_b <<<node16_grid, 256>>>(b1, W2, n);                 // aggr1 + relu + .W2
    k_fused_c <<<(n + 255) / 256, 256>>>(b2, Wm1, bm1, Wm2, bm2, out, n);
}

// round 17
// speedup vs baseline: 1.2138x; 1.1373x over previous
#include <cuda_runtime.h>
#include <cuda_fp16.h>
#include <cstdint>

#define NN  100000
#define EE  1200000
#define FIN 128
#define HID 64
#define SCAN_TILE 256
#define MAX_PARTS ((NN + SCAN_TILE - 1) / SCAN_TILE)   // 391

// Scratch (static __device__ arrays — no allocation allowed)
__device__ __align__(256) __half g_ysh [(size_t)NN * HID];  // layer-0 out -> prescaled by dinv
__device__ __align__(256) __half g_ys2h[(size_t)NN * HID];  // layer-1 out (prescaled by dinv)
__device__ __align__(256) float g_dinv[NN];
__device__ __align__(256) int   g_cnt[NN];
__device__ __align__(256) int   g_off[NN + 1];
__device__ __align__(256) int   g_cur[NN];
__device__ __align__(256) int   g_part[MAX_PARTS];
__device__ __align__(256) int   g_srcs[EE];                // dst-sorted source ids (CSR)
__device__ __align__(256) float g_s1[NN];                  // scalar layer source
__device__ int g_is64;

// ---------- f32x2 packed-FMA helpers ----------
__device__ __forceinline__ unsigned long long ffma2(unsigned long long a,
                                                    unsigned long long b,
                                                    unsigned long long c) {
    unsigned long long d;
    asm("fma.rn.f32x2 %0, %1, %2, %3;" : "=l"(d) : "l"(a), "l"(b), "l"(c));
    return d;
}
__device__ __forceinline__ unsigned long long dup2(float x) {
    unsigned long long d;
    unsigned int u = __float_as_uint(x);
    asm("mov.b64 %0, {%1, %1};" : "=l"(d) : "r"(u));
    return d;
}

// ---------- fp16 helpers ----------
__device__ __forceinline__ void cvt8f(uint4 u, float* f) {
    float2 f0 = __half22float2(*reinterpret_cast<__half2*>(&u.x));
    float2 f1 = __half22float2(*reinterpret_cast<__half2*>(&u.y));
    float2 f2 = __half22float2(*reinterpret_cast<__half2*>(&u.z));
    float2 f3 = __half22float2(*reinterpret_cast<__half2*>(&u.w));
    f[0]=f0.x; f[1]=f0.y; f[2]=f1.x; f[3]=f1.y;
    f[4]=f2.x; f[5]=f2.y; f[6]=f3.x; f[7]=f3.y;
}
__device__ __forceinline__ uint4 hadd2x4(uint4 a, uint4 b) {
    uint4 r;
    *reinterpret_cast<__half2*>(&r.x) = __hadd2(*reinterpret_cast<__half2*>(&a.x),
                                                *reinterpret_cast<__half2*>(&b.x));
    *reinterpret_cast<__half2*>(&r.y) = __hadd2(*reinterpret_cast<__half2*>(&a.y),
                                                *reinterpret_cast<__half2*>(&b.y));
    *reinterpret_cast<__half2*>(&r.z) = __hadd2(*reinterpret_cast<__half2*>(&a.z),
                                                *reinterpret_cast<__half2*>(&b.z));
    *reinterpret_cast<__half2*>(&r.w) = __hadd2(*reinterpret_cast<__half2*>(&a.w),
                                                *reinterpret_cast<__half2*>(&b.w));
    return r;
}
__device__ __forceinline__ void addcvt8(float* acc, uint4 u) {
    float t[8];
    cvt8f(u, t);
#pragma unroll
    for (int q = 0; q < 8; q++) acc[q] += t[q];
}
__device__ __forceinline__ void st_half4(__half* p, float4 v) {
    __half2 h01 = __floats2half2_rn(v.x, v.y);
    __half2 h23 = __floats2half2_rn(v.z, v.w);
    uint2 u;
    u.x = *reinterpret_cast<unsigned int*>(&h01);
    u.y = *reinterpret_cast<unsigned int*>(&h23);
    *reinterpret_cast<uint2*>(p) = u;
}

__device__ __forceinline__ int edge_at(const void* ei, int is64, size_t idx) {
    if (is64) return (int)((const long long*)ei)[idx];
    return ((const int*)ei)[idx];
}

// ---------- zero + edge-dtype detection (merged) ----------
__global__ void k_zero_detect(const long long* ei, int e, int n) {
    int i = blockIdx.x * blockDim.x + threadIdx.x;
    if (i < n) g_cnt[i] = 0;
    if (blockIdx.x == 0 && threadIdx.x < 32) {
        int t = threadIdx.x;
        int m = e < 32 ? e : 32;
        int bad = 0;
        if (t < m) {
            long long v = ei[t];
            if (v < 0 || v >= NN) bad = 1;
        }
        unsigned int anybad = __ballot_sync(0xffffffffu, bad);
        if (t == 0) g_is64 = (anybad == 0u);
    }
}

// ---------- CSR build: histogram (2 edges/thread) ----------
__global__ void k_count(const void* ei, int e) {
    int i = blockIdx.x * blockDim.x + threadIdx.x;
    int is64 = g_is64;
    if (!(e & 1)) {
        int i2 = i * 2;
        if (i2 >= e) return;
        int d0, d1;
        if (is64) {
            ulonglong2 v = reinterpret_cast<const ulonglong2*>(ei)[((size_t)e + i2) >> 1];
            d0 = (int)v.x; d1 = (int)v.y;
        } else {
            int2 v = reinterpret_cast<const int2*>(ei)[((size_t)e + i2) >> 1];
            d0 = v.x; d1 = v.y;
        }
        if (d0 == d1) {
            atomicAdd(&g_cnt[d0], 2);
        } else {
            atomicAdd(&g_cnt[d0], 1);
            atomicAdd(&g_cnt[d1], 1);
        }
    } else {
        if (i >= e) return;
        int dst = edge_at(ei, is64, (size_t)e + i);
        atomicAdd(&g_cnt[dst], 1);
    }
}

__global__ __launch_bounds__(SCAN_TILE) void k_blocksum(int n) {
    __shared__ int wsum[SCAN_TILE / 32];
    int t = threadIdx.x;
    int i = blockIdx.x * SCAN_TILE + t;
    int v = (i < n) ? g_cnt[i] : 0;
#pragma unroll
    for (int d = 16; d > 0; d >>= 1) v += __shfl_down_sync(0xffffffffu, v, d);
    if ((t & 31) == 0) wsum[t >> 5] = v;
    __syncthreads();
    if (t < SCAN_TILE / 32) {
        int s = wsum[t];
#pragma unroll
        for (int d = (SCAN_TILE / 64); d > 0; d >>= 1)
            s += __shfl_down_sync(0xffu, s, d);
        if (t == 0) g_part[blockIdx.x] = s;
    }
}

// merged: per-block prefix over g_part (warp 0) + intra-block scan; emits off/cur/dinv
__global__ __launch_bounds__(SCAN_TILE) void k_finaloff(int nb, int n) {
    __shared__ int wexc[SCAN_TILE / 32];
    __shared__ int s_base;
    int t = threadIdx.x;

    if (t < 32) {
        int sum = 0;
        for (int i = t; i < blockIdx.x; i += 32) sum += g_part[i];
#pragma unroll
        for (int d = 16; d > 0; d >>= 1) sum += __shfl_down_sync(0xffffffffu, sum, d);
        if (t == 0) s_base = sum;
    }

    int i = blockIdx.x * SCAN_TILE + t;
    int c = (i < n) ? g_cnt[i] : 0;
    int lane = t & 31, warp = t >> 5;
    int inc = c;
#pragma unroll
    for (int d = 1; d < 32; d <<= 1) {
        int v = __shfl_up_sync(0xffffffffu, inc, d);
        if (lane >= d) inc += v;
    }
    if (lane == 31) wexc[warp] = inc;
    __syncthreads();
    if (t < SCAN_TILE / 32) {
        int v = wexc[t];
        int e2 = v;
#pragma unroll
        for (int d = 1; d < SCAN_TILE / 32; d <<= 1) {
            int u = __shfl_up_sync(0xffu, e2, d);
            if (t >= d) e2 += u;
        }
        wexc[t] = e2 - v;
    }
    __syncthreads();

    int off = s_base + wexc[warp] + (inc - c);
    if (i < n) {
        g_off[i] = off;
        g_cur[i] = off;
        g_dinv[i] = rsqrtf(1.0f + (float)c);
    }
    if (blockIdx.x == nb - 1 && t == SCAN_TILE - 1)
        g_off[n] = off + c;
}

// ---------- fill (2 edges/thread) ----------
__global__ void k_fill(const void* ei, int e) {
    int i = blockIdx.x * blockDim.x + threadIdx.x;
    int is64 = g_is64;
    if (!(e & 1)) {
        int i2 = i * 2;
        if (i2 >= e) return;
        int s0, s1, d0, d1;
        if (is64) {
            ulonglong2 sv = reinterpret_cast<const ulonglong2*>(ei)[(size_t)i2 >> 1];
            ulonglong2 dv = reinterpret_cast<const ulonglong2*>(ei)[((size_t)e + i2) >> 1];
            s0 = (int)sv.x; s1 = (int)sv.y;
            d0 = (int)dv.x; d1 = (int)dv.y;
        } else {
            int2 sv = reinterpret_cast<const int2*>(ei)[(size_t)i2 >> 1];
            int2 dv = reinterpret_cast<const int2*>(ei)[((size_t)e + i2) >> 1];
            s0 = sv.x; s1 = sv.y;
            d0 = dv.x; d1 = dv.y;
        }
        if (d0 == d1) {
            int pos = atomicAdd(&g_cur[d0], 2);
            g_srcs[pos] = s0;
            g_srcs[pos + 1] = s1;
        } else {
            g_srcs[atomicAdd(&g_cur[d0], 1)] = s0;
            g_srcs[atomicAdd(&g_cur[d1], 1)] = s1;
        }
    } else {
        if (i >= e) return;
        int src = edge_at(ei, is64, (size_t)i);
        int dst = edge_at(ei, is64, (size_t)e + i);
        g_srcs[atomicAdd(&g_cur[dst], 1)] = src;
    }
}

// ---------- prescale: ysh *= dinv[row] (z = dinv ⊙ ys), 8 threads/node ----------
__global__ void k_scale(int n) {
    int t = blockIdx.x * blockDim.x + threadIdx.x;
    int node = t >> 3;
    if (node >= n) return;
    int part = t & 7;
    __half* p = g_ysh + (size_t)node * HID + part * 8;
    uint4 u = *reinterpret_cast<const uint4*>(p);
    float f[8];
    cvt8f(u, f);
    float dv = g_dinv[node];
    uint4 o;
    __half2 h;
    h = __floats2half2_rn(f[0] * dv, f[1] * dv); o.x = *reinterpret_cast<unsigned int*>(&h);
    h = __floats2half2_rn(f[2] * dv, f[3] * dv); o.y = *reinterpret_cast<unsigned int*>(&h);
    h = __floats2half2_rn(f[4] * dv, f[5] * dv); o.z = *reinterpret_cast<unsigned int*>(&h);
    h = __floats2half2_rn(f[6] * dv, f[7] * dv); o.w = *reinterpret_cast<unsigned int*>(&h);
    *reinterpret_cast<uint4*>(p) = o;
}

// ---------- pull of one node-part from PRESCALED fp16 source ----------
// acc = z_v + sum_u z_u  (caller multiplies by dv); part covers 8 halves (16B).
__device__ __forceinline__ void aggr8(const __half* __restrict__ z,
                                      int node, int part, float* acc) {
    const __half* base = z + (size_t)part * 8;
    uint4 self = *reinterpret_cast<const uint4*>(base + (size_t)node * HID);
    cvt8f(self, acc);
    int j = g_off[node], end = g_off[node + 1];
#pragma unroll 2
    for (; j + 2 <= end; j += 2) {
        int s0 = g_srcs[j], s1 = g_srcs[j + 1];
        uint4 r0 = *reinterpret_cast<const uint4*>(base + (size_t)s0 * HID);
        uint4 r1 = *reinterpret_cast<const uint4*>(base + (size_t)s1 * HID);
        addcvt8(acc, hadd2x4(r0, r1));           // pairwise half add, fp32 accumulate
    }
    if (j < end) {
        int s = g_srcs[j];
        uint4 r = *reinterpret_cast<const uint4*>(base + (size_t)s * HID);
        addcvt8(acc, r);
    }
}

// ---------- tiled SGEMM (f32x2 packed): ysh = fp16(A @ W)  (layer 0, K=128) ----------
template <int K>
__global__ __launch_bounds__(256)
void k_gemm(const float* __restrict__ A, const float* __restrict__ W, int n) {
    constexpr int BM = 128, BN = 64, BK = 16;
    __shared__ float Ws[K * BN];
    __shared__ float As[BK][BM];

    int tid = threadIdx.x;
    for (int i = tid; i < (K * BN) / 4; i += 256)
        reinterpret_cast<float4*>(Ws)[i] = reinterpret_cast<const float4*>(W)[i];

    int tx = tid & 15;
    int ty = tid >> 4;
    int row0 = blockIdx.x * BM;

    unsigned long long acc2[4][4];
#pragma unroll
    for (int r = 0; r < 4; r++)
#pragma unroll
        for (int c = 0; c < 4; c++) acc2[r][c] = 0ULL;

    for (int k0 = 0; k0 < K; k0 += BK) {
        __syncthreads();
#pragma unroll
        for (int l = 0; l < 2; l++) {
            int lin = tid + l * 256;
            int row = lin & 127;
            int kq  = lin >> 7;
            int grow = row0 + row;
            float4 v = make_float4(0.f, 0.f, 0.f, 0.f);
            if (grow < n)
                v = *reinterpret_cast<const float4*>(A + (size_t)grow * K + k0 + kq * 4);
            As[kq * 4 + 0][row] = v.x;
            As[kq * 4 + 1][row] = v.y;
            As[kq * 4 + 2][row] = v.z;
            As[kq * 4 + 3][row] = v.w;
        }
        __syncthreads();

#pragma unroll
        for (int k = 0; k < BK; k++) {
            float4 b = *reinterpret_cast<const float4*>(&Ws[(k0 + k) * BN + tx * 4]);
            unsigned long long bp[4] = {dup2(b.x), dup2(b.y), dup2(b.z), dup2(b.w)};
            const ulonglong2* ar = reinterpret_cast<const ulonglong2*>(&As[k][ty * 8]);
            ulonglong2 a01 = ar[0];
            ulonglong2 a23 = ar[1];
            unsigned long long ap[4] = {a01.x, a01.y, a23.x, a23.y};
#pragma unroll
            for (int r = 0; r < 4; r++)
#pragma unroll
                for (int c = 0; c < 4; c++)
                    acc2[r][c] = ffma2(ap[r], bp[c], acc2[r][c]);
        }
    }

#pragma unroll
    for (int r = 0; r < 4; r++) {
        int ge = row0 + ty * 8 + 2 * r;
        float2 c0 = *reinterpret_cast<float2*>(&acc2[r][0]);
        float2 c1 = *reinterpret_cast<float2*>(&acc2[r][1]);
        float2 c2 = *reinterpret_cast<float2*>(&acc2[r][2]);
        float2 c3 = *reinterpret_cast<float2*>(&acc2[r][3]);
        if (ge < n)
            st_half4(g_ysh + (size_t)ge * HID + tx * 4,
                     make_float4(c0.x, c1.x, c2.x, c3.x));
        if (ge + 1 < n)
            st_half4(g_ysh + (size_t)(ge + 1) * HID + tx * 4,
                     make_float4(c0.y, c1.y, c2.y, c3.y));
    }
}

// ---------- FUSED: aggr(prescaled ysh) -> relu(dv*acc+b0) -> @W1 -> dinv⊙out -> ys2h ----------
__global__ __launch_bounds__(256)
void k_fused_ag(const float* __restrict__ W, const float* __restrict__ bias, int n) {
    constexpr int BM = 128, BN = 64, K = 64, AST = 132;
    __shared__ float Ws[K * BN];          // 16 KB
    __shared__ float As[K][AST];          // 33.8 KB (bank-conflict-free via row permute)

    int tid = threadIdx.x;
    for (int i = tid; i < (K * BN) / 4; i += 256)
        reinterpret_cast<float4*>(Ws)[i] = reinterpret_cast<const float4*>(W)[i];

    int row0 = blockIdx.x * BM;
    int part = tid & 7;       // 16B feature slice
    int grp  = tid >> 3;      // 0..31 node groups

    float4 ba = __ldg(reinterpret_cast<const float4*>(bias + part * 8));
    float4 bb = __ldg(reinterpret_cast<const float4*>(bias + part * 8 + 4));
    float bq[8] = {ba.x, ba.y, ba.z, ba.w, bb.x, bb.y, bb.z, bb.w};

    // aggregation phase: 4 passes x 32 nodes
#pragma unroll 1
    for (int p = 0; p < 4; p++) {
        int nl = p * 32 + grp;
        int node = row0 + nl;
        float a[8];
#pragma unroll
        for (int q = 0; q < 8; q++) a[q] = 0.0f;
        float dv = 0.0f;
        if (node < n) {
            aggr8(g_ysh, node, part, a);
            dv = g_dinv[node];
        }
#pragma unroll
        for (int q = 0; q < 8; q++) {
            float v = fmaxf(fmaf(a[q], dv, (node < n) ? bq[q] : 0.0f), 0.0f);
            As[part * 8 + ((q + part) & 7)][nl] = v;    // permuted row -> no bank conflict
        }
    }
    __syncthreads();

    // GEMM phase (reads undo the row permutation at compile time)
    int tx = tid & 15;
    int ty = tid >> 4;
    unsigned long long acc2[4][4];
#pragma unroll
    for (int r = 0; r < 4; r++)
#pragma unroll
        for (int c = 0; c < 4; c++) acc2[r][c] = 0ULL;

#pragma unroll 8
    for (int k = 0; k < K; k++) {
        int kp = (k & ~7) | (((k & 7) + (k >> 3)) & 7);
        float4 b = *reinterpret_cast<const float4*>(&Ws[k * BN + tx * 4]);
        unsigned long long bp[4] = {dup2(b.x), dup2(b.y), dup2(b.z), dup2(b.w)};
        const ulonglong2* ar = reinterpret_cast<const ulonglong2*>(&As[kp][ty * 8]);
        ulonglong2 a01 = ar[0];
        ulonglong2 a23 = ar[1];
        unsigned long long ap[4] = {a01.x, a01.y, a23.x, a23.y};
#pragma unroll
        for (int r = 0; r < 4; r++)
#pragma unroll
            for (int c = 0; c < 4; c++)
                acc2[r][c] = ffma2(ap[r], bp[c], acc2[r][c]);
    }

#pragma unroll
    for (int r = 0; r < 4; r++) {
        int ge = row0 + ty * 8 + 2 * r;
        float2 c0 = *reinterpret_cast<float2*>(&acc2[r][0]);
        float2 c1 = *reinterpret_cast<float2*>(&acc2[r][1]);
        float2 c2 = *reinterpret_cast<float2*>(&acc2[r][2]);
        float2 c3 = *reinterpret_cast<float2*>(&acc2[r][3]);
        if (ge < n) {
            float dva = g_dinv[ge];
            st_half4(g_ys2h + (size_t)ge * HID + tx * 4,
                     make_float4(c0.x * dva, c1.x * dva, c2.x * dva, c3.x * dva));
        }
        if (ge + 1 < n) {
            float dvb = g_dinv[ge + 1];
            st_half4(g_ys2h + (size_t)(ge + 1) * HID + tx * 4,
                     make_float4(c0.y * dvb, c1.y * dvb, c2.y * dvb, c3.y * dvb));
        }
    }
}

// ---------- FUSED: aggr(prescaled ys2h) -> relu(dv*acc+b1) -> dot W2 -> s1 = dv * dot ----------
__global__ void k_fused_b(const float* __restrict__ b1,
                          const float* __restrict__ W2, int n) {
    int t = blockIdx.x * blockDim.x + threadIdx.x;
    int node = t >> 3;
    if (node >= n) return;
    int part = t & 7;

    float a[8];
    aggr8(g_ys2h, node, part, a);
    float dv = g_dinv[node];

    float4 b1a = __ldg(reinterpret_cast<const float4*>(b1 + part * 8));
    float4 b1b = __ldg(reinterpret_cast<const float4*>(b1 + part * 8 + 4));
    float4 w2a = __ldg(reinterpret_cast<const float4*>(W2 + part * 8));
    float4 w2b = __ldg(reinterpret_cast<const float4*>(W2 + part * 8 + 4));

    float s = fmaxf(fmaf(a[0], dv, b1a.x), 0.0f) * w2a.x
            + fmaxf(fmaf(a[1], dv, b1a.y), 0.0f) * w2a.y
            + fmaxf(fmaf(a[2], dv, b1a.z), 0.0f) * w2a.z
            + fmaxf(fmaf(a[3], dv, b1a.w), 0.0f) * w2a.w
            + fmaxf(fmaf(a[4], dv, b1b.x), 0.0f) * w2b.x
            + fmaxf(fmaf(a[5], dv, b1b.y), 0.0f) * w2b.y
            + fmaxf(fmaf(a[6], dv, b1b.z), 0.0f) * w2b.z
            + fmaxf(fmaf(a[7], dv, b1b.w), 0.0f) * w2b.w;
#pragma unroll
    for (int d = 4; d > 0; d >>= 1)
        s += __shfl_down_sync(0xffffffffu, s, d, 8);
    if (part == 0) g_s1[node] = s * dv;
}

// ---------- FUSED: scalar aggr(s1) -> +b2 -> MLP head -> out ----------
__global__ void k_fused_c(const float* __restrict__ b2,
                          const float* __restrict__ Wm1,
                          const float* __restrict__ bm1,
                          const float* __restrict__ Wm2,
                          const float* __restrict__ bm2,
                          float* __restrict__ out, int n) {
    int i = blockIdx.x * blockDim.x + threadIdx.x;
    if (i >= n) return;
    float s = g_s1[i];
    int j   = g_off[i];
    int end = g_off[i + 1];
    for (; j + 4 <= end; j += 4) {
        float v0 = g_s1[g_srcs[j + 0]];
        float v1 = g_s1[g_srcs[j + 1]];
        float v2 = g_s1[g_srcs[j + 2]];
        float v3 = g_s1[g_srcs[j + 3]];
        s += v0 + v1 + v2 + v3;
    }
    for (; j < end; j++) s += g_s1[g_srcs[j]];
    float h2 = fmaf(s, g_dinv[i], __ldg(b2));

    const float4* w1 = reinterpret_cast<const float4*>(Wm1);
    const float4* bb = reinterpret_cast<const float4*>(bm1);
    const float4* w2 = reinterpret_cast<const float4*>(Wm2);
    float o = __ldg(bm2);
#pragma unroll
    for (int j4 = 0; j4 < HID / 4; j4++) {
        float4 a = __ldg(&w1[j4]);
        float4 b = __ldg(&bb[j4]);
        float4 c = __ldg(&w2[j4]);
        o += fmaxf(fmaf(h2, a.x, b.x), 0.0f) * c.x;
        o += fmaxf(fmaf(h2, a.y, b.y), 0.0f) * c.y;
        o += fmaxf(fmaf(h2, a.z, b.z), 0.0f) * c.z;
        o += fmaxf(fmaf(h2, a.w, b.w), 0.0f) * c.w;
    }
    out[i] = o;
}

extern "C" void kernel_launch(void* const* d_in, const int* in_sizes, int n_in,
                              void* d_out, int out_size) {
    const float* x   = (const float*)d_in[0];
    const void*  ei  = d_in[1];
    const float* W0  = (const float*)d_in[2];
    const float* b0  = (const float*)d_in[3];
    const float* W1  = (const float*)d_in[4];
    const float* b1  = (const float*)d_in[5];
    const float* W2  = (const float*)d_in[6];
    const float* b2  = (const float*)d_in[7];
    const float* Wm1 = (const float*)d_in[8];
    const float* bm1 = (const float*)d_in[9];
    const float* Wm2 = (const float*)d_in[10];
    const float* bm2 = (const float*)d_in[11];
    float* out = (float*)d_out;

    int n = in_sizes[0] / FIN;   // 100000
    int e = in_sizes[1] / 2;     // 1200000
    int nb = (n + SCAN_TILE - 1) / SCAN_TILE;   // 391

    static cudaStream_t sB = nullptr;
    static cudaEvent_t evFork = nullptr, evCsr = nullptr, evJoin = nullptr;
    if (sB == nullptr) {
        cudaStreamCreateWithFlags(&sB, cudaStreamNonBlocking);
        cudaEventCreateWithFlags(&evFork, cudaEventDisableTiming);
        cudaEventCreateWithFlags(&evCsr,  cudaEventDisableTiming);
        cudaEventCreateWithFlags(&evJoin, cudaEventDisableTiming);
    }

    int gemm_grid = (n + 127) / 128;
    int node8_grid = (n * 8 + 255) / 256;
    int epair = (e & 1) ? e : e / 2;

    // ---- fork: GEMM0 (independent of graph structure) on sB ----
    cudaEventRecord(evFork, 0);
    cudaStreamWaitEvent(sB, evFork, 0);
    k_gemm<FIN><<<gemm_grid, 256, 0, sB>>>(x, W0, n);

    // ---- CSR build (to dinv) on default stream, concurrent with GEMM0 ----
    k_zero_detect<<<(n + 255) / 256, 256>>>((const long long*)ei, e, n);
    k_count<<<(epair + 255) / 256, 256>>>(ei, e);
    k_blocksum<<<nb, SCAN_TILE>>>(n);
    k_finaloff<<<nb, SCAN_TILE>>>(nb, n);
    cudaEventRecord(evCsr, 0);

    // ---- sB: prescale ysh by dinv once both GEMM0 and dinv are ready ----
    cudaStreamWaitEvent(sB, evCsr, 0);
    k_scale<<<node8_grid, 256, 0, sB>>>(n);
    cudaEventRecord(evJoin, sB);

    // ---- default: fill CSR adjacency (overlaps k_scale) ----
    k_fill<<<(epair + 255) / 256, 256>>>(ei, e);

    // ---- join ----
    cudaStreamWaitEvent(0, evJoin, 0);

    // fused layer chain
    k_fused_ag<<<gemm_grid, 256>>>(W1, b0, n);                   // aggr0 + relu + @W1 (+dinv)
    k_fused_b <<<node8_grid, 256>>>(b1, W2, n);                  // aggr1 + relu + .W2
    k_fused_c <<<(n + 255) / 256, 256>>>(b2, Wm1, bm1, Wm2, bm2, out, n);
}